// round 15
// baseline (speedup 1.0000x reference)
#include <cuda_runtime.h>
#include <cstdint>

// DangoCutouts: 16 x (3,512,512) fp32 outputs from one (3,4096,4096) image.
// grid.y==0 : overview — one bilinear gather serves images 0,1,2,3.
// grid.y>=1 : random crops (crop 0 grayed), processed in offy-sorted order
//             (per-block smem permutation).
// 4 output rows per thread (y-unroll); lane-consecutive x; streaming stores.

#define H 4096
#define W 4096
#define CUT 512
#define CH_STRIDE (4096u * 4096u)
#define PLANE (CUT * CUT)
#define N_INNER 12
#define TPB 512
#define RPT 4   // rows per thread

struct Taps { int x0, x1; float wx; };

__device__ __forceinline__ Taps tap1d(int o, int size, float s, float sc, int i)
{
    float f = (float)o + (((float)i + 0.5f) * sc - 0.5f);
    f = fminf(fmaxf(f, (float)o), (float)o + s - 1.0f);
    Taps t;
    t.x0 = (int)floorf(f);
    t.x1 = min(t.x0 + 1, o + size - 1);
    t.wx = f - (float)t.x0;
    return t;
}

__global__ __launch_bounds__(TPB)
void dango_cutouts_kernel(const float* __restrict__ img,
                          const int*   __restrict__ sizes,
                          const int*   __restrict__ offy,
                          const int*   __restrict__ offx,
                          float*       __restrict__ out)
{
    const int p  = blockIdx.x * TPB + threadIdx.x;          // 0 .. 512*128-1
    const int g  = blockIdx.y;                               // 0 .. 12
    const int xo = p & 511;                                  // lane-consecutive x
    const int yo = (p >> 9) << 2;                            // first of 4 rows

    // Per-block offy-sorted permutation: sperm[rank] = crop index.
    __shared__ int sperm[N_INNER];
    if (threadIdx.x < N_INNER) {
        const int cand = threadIdx.x;
        const int oyc  = __ldg(offy + cand);
        int rank = 0;
#pragma unroll
        for (int k = 0; k < N_INNER; ++k) {
            const int oyk = __ldg(offy + k);
            rank += (oyk < oyc) || (oyk == oyc && k < cand);
        }
        sperm[rank] = cand;
    }
    __syncthreads();

    int oy, ox, sz, j = -1;
    if (g == 0) { oy = 0; ox = 0; sz = 4096; }
    else {
        j  = sperm[g - 1];
        oy = __ldg(offy  + j);
        ox = __ldg(offx  + j);
        sz = __ldg(sizes + j);
    }

    const float s  = (float)sz;
    const float sc = s * (1.0f / 512.0f);   // exact pow2 scale

    const Taps tx = tap1d(ox, sz, s, sc, xo);

    size_t r0[RPT], r1[RPT];
    float  wy[RPT];
#pragma unroll
    for (int r = 0; r < RPT; ++r) {
        const Taps ty = tap1d(oy, sz, s, sc, yo + r);
        r0[r] = (size_t)ty.x0 * W;
        r1[r] = (size_t)ty.x1 * W;
        wy[r] = ty.wx;
    }

    float v[RPT][3];
#pragma unroll
    for (int c = 0; c < 3; ++c) {
        const float* base = img + (size_t)c * CH_STRIDE;
#pragma unroll
        for (int r = 0; r < RPT; ++r) {
            const float v00 = __ldg(base + r0[r] + tx.x0);
            const float v01 = __ldg(base + r0[r] + tx.x1);
            const float v10 = __ldg(base + r1[r] + tx.x0);
            const float v11 = __ldg(base + r1[r] + tx.x1);
            const float top = v00 + (v01 - v00) * tx.wx;
            const float bot = v10 + (v11 - v10) * tx.wx;
            v[r][c] = top + (bot - top) * wy[r];
        }
    }

    if (g == 0) {
#pragma unroll
        for (int r = 0; r < RPT; ++r) {
            const float gr = 0.2989f * v[r][0] + 0.587f * v[r][1] + 0.114f * v[r][2];
            const size_t row = (size_t)(yo + r) * CUT;
            const size_t pf  = row + xo;
            const size_t pr  = row + (511 - xo);
#pragma unroll
            for (int c = 0; c < 3; ++c) {
                const size_t cp = (size_t)c * PLANE;
                __stcs(out + 0 * PLANE + cp + pf, v[r][c]);   // img0 full
                __stcs(out + 3 * PLANE + cp + pf, gr);        // img1 gray
                __stcs(out + 6 * PLANE + cp + pr, v[r][c]);   // img2 flip
                __stcs(out + 9 * PLANE + cp + pr, gr);        // img3 gray-flip
            }
        }
    } else {
        if (j == 0) {   // crop 0 (original index) is grayed
#pragma unroll
            for (int r = 0; r < RPT; ++r) {
                const float gr = 0.2989f * v[r][0] + 0.587f * v[r][1] + 0.114f * v[r][2];
                v[r][0] = v[r][1] = v[r][2] = gr;
            }
        }
        const size_t obase = ((size_t)(j + 4) * 3) * PLANE + (size_t)yo * CUT + xo;
#pragma unroll
        for (int c = 0; c < 3; ++c) {
#pragma unroll
            for (int r = 0; r < RPT; ++r)
                __stcs(out + obase + (size_t)c * PLANE + (size_t)r * CUT, v[r][c]);
        }
    }
}

extern "C" void kernel_launch(void* const* d_in, const int* in_sizes, int n_in,
                              void* d_out, int out_size)
{
    const float* img   = (const float*)d_in[0];
    // d_in[1] = t (unused)
    const int*   sizes = (const int*)d_in[2];
    const int*   offy  = (const int*)d_in[3];
    const int*   offx  = (const int*)d_in[4];
    float*       out   = (float*)d_out;

    dim3 block(TPB, 1, 1);
    dim3 grid((PLANE / RPT) / TPB, 13, 1);
    dango_cutouts_kernel<<<grid, block>>>(img, sizes, offy, offx, out);
}

// round 16
// speedup vs baseline: 1.2145x; 1.2145x over previous
#include <cuda_runtime.h>
#include <cstdint>

// DangoCutouts: 16 x (3,512,512) fp32 outputs from one (3,4096,4096) image.
// blockIdx.x = image slot (13: overview + 12 crops, offy-sorted order)  <- FAST dim
// blockIdx.y = row chunk (512)                                          <- SLOW dim
// => concurrently-resident CTAs cover a narrow source-row band of ALL images
//    simultaneously (banded co-scheduling) instead of 2-3 whole images,
//    shrinking the live L2 working set.
// 2 output pixels per thread in y; lane-consecutive x; streaming stores.

#define H 4096
#define W 4096
#define CUT 512
#define CH_STRIDE (4096u * 4096u)
#define PLANE (CUT * CUT)
#define N_INNER 12
#define TPB 256

struct Taps { int x0, x1; float wx; };

__device__ __forceinline__ Taps tap1d(int o, int size, float s, float sc, int i)
{
    float f = (float)o + (((float)i + 0.5f) * sc - 0.5f);
    f = fminf(fmaxf(f, (float)o), (float)o + s - 1.0f);
    Taps t;
    t.x0 = (int)floorf(f);
    t.x1 = min(t.x0 + 1, o + size - 1);
    t.wx = f - (float)t.x0;
    return t;
}

__global__ __launch_bounds__(TPB)
void dango_cutouts_kernel(const float* __restrict__ img,
                          const int*   __restrict__ sizes,
                          const int*   __restrict__ offy,
                          const int*   __restrict__ offx,
                          float*       __restrict__ out)
{
    const int p  = blockIdx.y * TPB + threadIdx.x;          // 0 .. 512*256-1
    const int g  = blockIdx.x;                               // 0 .. 12 (fast dim)
    const int xo = p & 511;                                  // lane-consecutive x
    const int yo = (p >> 9) << 1;                            // first of 2 rows

    // Per-block offy-sorted permutation: sperm[rank] = crop index.
    __shared__ int sperm[N_INNER];
    if (threadIdx.x < N_INNER) {
        const int cand = threadIdx.x;
        const int oyc  = __ldg(offy + cand);
        int rank = 0;
#pragma unroll
        for (int k = 0; k < N_INNER; ++k) {
            const int oyk = __ldg(offy + k);
            rank += (oyk < oyc) || (oyk == oyc && k < cand);
        }
        sperm[rank] = cand;
    }
    __syncthreads();

    int oy, ox, sz, j = -1;
    if (g == 0) { oy = 0; ox = 0; sz = 4096; }
    else {
        j  = sperm[g - 1];
        oy = __ldg(offy  + j);
        ox = __ldg(offx  + j);
        sz = __ldg(sizes + j);
    }

    const float s  = (float)sz;
    const float sc = s * (1.0f / 512.0f);   // exact pow2 scale

    const Taps tx = tap1d(ox, sz, s, sc, xo);
    const Taps ya = tap1d(oy, sz, s, sc, yo);
    const Taps yb = tap1d(oy, sz, s, sc, yo + 1);

    const size_t r0a = (size_t)ya.x0 * W;
    const size_t r1a = (size_t)ya.x1 * W;
    const size_t r0b = (size_t)yb.x0 * W;
    const size_t r1b = (size_t)yb.x1 * W;

    float va[3], vb[3];
#pragma unroll
    for (int c = 0; c < 3; ++c) {
        const float* base = img + (size_t)c * CH_STRIDE;
        const float a00 = __ldg(base + r0a + tx.x0);
        const float a01 = __ldg(base + r0a + tx.x1);
        const float a10 = __ldg(base + r1a + tx.x0);
        const float a11 = __ldg(base + r1a + tx.x1);
        const float b00 = __ldg(base + r0b + tx.x0);
        const float b01 = __ldg(base + r0b + tx.x1);
        const float b10 = __ldg(base + r1b + tx.x0);
        const float b11 = __ldg(base + r1b + tx.x1);

        const float atop = a00 + (a01 - a00) * tx.wx;
        const float abot = a10 + (a11 - a10) * tx.wx;
        const float btop = b00 + (b01 - b00) * tx.wx;
        const float bbot = b10 + (b11 - b10) * tx.wx;
        va[c] = atop + (abot - atop) * ya.wx;
        vb[c] = btop + (bbot - btop) * yb.wx;
    }

    if (g == 0) {
        const float ga = 0.2989f * va[0] + 0.587f * va[1] + 0.114f * va[2];
        const float gb = 0.2989f * vb[0] + 0.587f * vb[1] + 0.114f * vb[2];
        const size_t rowa = (size_t)yo * CUT;
        const size_t rowb = rowa + CUT;
        const size_t pfa = rowa + xo,  pra = rowa + (511 - xo);
        const size_t pfb = rowb + xo,  prb = rowb + (511 - xo);
#pragma unroll
        for (int c = 0; c < 3; ++c) {
            const size_t cp = (size_t)c * PLANE;
            __stcs(out + 0 * PLANE + cp + pfa, va[c]);   // img0 full
            __stcs(out + 0 * PLANE + cp + pfb, vb[c]);
            __stcs(out + 3 * PLANE + cp + pfa, ga);      // img1 gray
            __stcs(out + 3 * PLANE + cp + pfb, gb);
            __stcs(out + 6 * PLANE + cp + pra, va[c]);   // img2 flip
            __stcs(out + 6 * PLANE + cp + prb, vb[c]);
            __stcs(out + 9 * PLANE + cp + pra, ga);      // img3 gray-flip
            __stcs(out + 9 * PLANE + cp + prb, gb);
        }
    } else {
        if (j == 0) {   // crop 0 (original index) is grayed
            const float ga = 0.2989f * va[0] + 0.587f * va[1] + 0.114f * va[2];
            const float gb = 0.2989f * vb[0] + 0.587f * vb[1] + 0.114f * vb[2];
            va[0] = va[1] = va[2] = ga;
            vb[0] = vb[1] = vb[2] = gb;
        }
        const size_t obase = ((size_t)(j + 4) * 3) * PLANE + (size_t)yo * CUT + xo;
#pragma unroll
        for (int c = 0; c < 3; ++c) {
            __stcs(out + obase + (size_t)c * PLANE, va[c]);
            __stcs(out + obase + (size_t)c * PLANE + CUT, vb[c]);
        }
    }
}

extern "C" void kernel_launch(void* const* d_in, const int* in_sizes, int n_in,
                              void* d_out, int out_size)
{
    const float* img   = (const float*)d_in[0];
    // d_in[1] = t (unused)
    const int*   sizes = (const int*)d_in[2];
    const int*   offy  = (const int*)d_in[3];
    const int*   offx  = (const int*)d_in[4];
    float*       out   = (float*)d_out;

    dim3 block(TPB, 1, 1);
    dim3 grid(13, (PLANE / 2) / TPB, 1);   // image = fast dim, chunk = slow dim
    dango_cutouts_kernel<<<grid, block>>>(img, sizes, offy, offx, out);
}